// round 2
// baseline (speedup 1.0000x reference)
#include <cuda_runtime.h>
#include <math.h>

#define Bc   4
#define Sc   2048
#define HIDc 1024
#define Hc   16
#define Dc   64
#define MROWS (Bc*Sc)        // 8192
#define BHc  (Bc*Hc)         // 64
#define LOG2E 1.4426950408889634f

// Scratch (allocation-free __device__ globals)
__device__ float g_Q[(size_t)BHc * Sc * Dc];
__device__ float g_K[(size_t)BHc * Sc * Dc];
__device__ float g_V[(size_t)BHc * Sc * Dc];
__device__ float g_pm[(size_t)BHc * Sc * 16];   // partial row max  [bh][q][ntile]
__device__ float g_pl[(size_t)BHc * Sc * 16];   // partial sumexp   [bh][q][ntile]
__device__ float g_M [(size_t)BHc * Sc];        // final row max
__device__ float g_Li[(size_t)BHc * Sc];        // final 1/l

// ---------------------------------------------------------------------------
// Projection GEMM: C[m,n] = sum_k X[m,k] * W[n,k] + bias[n]
// 128x128 block tile, BK=16, 256 threads, 8x8 microtile.
// Output permuted into [B, H, S, D].
// ---------------------------------------------------------------------------
__global__ __launch_bounds__(256) void proj_kernel(
    const float* __restrict__ X, const float* __restrict__ W,
    const float* __restrict__ bias, float* __restrict__ out)
{
    __shared__ float As[16][132];
    __shared__ float Bs[16][132];

    const int tid = threadIdx.x;
    const int tx  = tid & 15;          // col group
    const int ty  = tid >> 4;          // row group
    const int m0  = blockIdx.y * 128;
    const int n0  = blockIdx.x * 128;

    float acc[8][8] = {};

    for (int k0 = 0; k0 < 1024; k0 += 16) {
        #pragma unroll
        for (int it = 0; it < 2; it++) {
            const int idx = tid + it * 256;     // 0..511
            const int row = idx >> 2;           // 0..127
            const int c4  = (idx & 3) * 4;      // 0,4,8,12
            float4 a = *(const float4*)&X[(size_t)(m0 + row) * 1024 + k0 + c4];
            As[c4 + 0][row] = a.x; As[c4 + 1][row] = a.y;
            As[c4 + 2][row] = a.z; As[c4 + 3][row] = a.w;
            float4 b = *(const float4*)&W[(size_t)(n0 + row) * 1024 + k0 + c4];
            Bs[c4 + 0][row] = b.x; Bs[c4 + 1][row] = b.y;
            Bs[c4 + 2][row] = b.z; Bs[c4 + 3][row] = b.w;
        }
        __syncthreads();

        #pragma unroll
        for (int kk = 0; kk < 16; kk++) {
            float4 a0 = *(const float4*)&As[kk][ty * 8];
            float4 a1 = *(const float4*)&As[kk][ty * 8 + 4];
            float4 b0 = *(const float4*)&Bs[kk][tx * 8];
            float4 b1 = *(const float4*)&Bs[kk][tx * 8 + 4];
            float av[8] = {a0.x,a0.y,a0.z,a0.w,a1.x,a1.y,a1.z,a1.w};
            float bv[8] = {b0.x,b0.y,b0.z,b0.w,b1.x,b1.y,b1.z,b1.w};
            #pragma unroll
            for (int i = 0; i < 8; i++)
                #pragma unroll
                for (int j = 0; j < 8; j++)
                    acc[i][j] += av[i] * bv[j];
        }
        __syncthreads();
    }

    #pragma unroll
    for (int i = 0; i < 8; i++) {
        const int m  = m0 + ty * 8 + i;
        const int b_ = m >> 11;
        const int s  = m & 2047;
        const int n  = n0 + tx * 8;     // multiple of 8, within one head (64)
        const int h  = n >> 6;
        const int d  = n & 63;
        float4 o0, o1;
        o0.x = acc[i][0] + bias[n+0]; o0.y = acc[i][1] + bias[n+1];
        o0.z = acc[i][2] + bias[n+2]; o0.w = acc[i][3] + bias[n+3];
        o1.x = acc[i][4] + bias[n+4]; o1.y = acc[i][5] + bias[n+5];
        o1.z = acc[i][6] + bias[n+6]; o1.w = acc[i][7] + bias[n+7];
        float* dst = &out[(((size_t)b_ * 16 + h) * 2048 + s) * 64 + d];
        *(float4*)dst = o0;
        *(float4*)(dst + 4) = o1;
    }
}

// ---------------------------------------------------------------------------
// Scores: per (b,h): s[q,k] = scale*Q.K^T, masked_fill; writes s to attn buf,
// emits per-(row, 128-col-block) (max, sumexp) partials.
// Grid: x=bh (fastest, for mask L2 reuse), y=ntile, z=mtile. 128x128 tile.
// ---------------------------------------------------------------------------
__global__ __launch_bounds__(256) void scores_kernel(
    const float* __restrict__ Q, const float* __restrict__ K,
    const int* __restrict__ mask, float* __restrict__ attn)
{
    const int bh = blockIdx.x;
    const int n0 = blockIdx.y * 128;
    const int m0 = blockIdx.z * 128;
    const float* Qh = Q + (size_t)bh * Sc * Dc;
    const float* Kh = K + (size_t)bh * Sc * Dc;
    float* Ph = attn + (size_t)bh * Sc * Sc;

    __shared__ float As[32][132];
    __shared__ float Bs[32][132];

    const int tid = threadIdx.x;
    const int tx  = tid & 15;
    const int ty  = tid >> 4;

    float acc[8][8] = {};

    #pragma unroll
    for (int k0 = 0; k0 < 64; k0 += 32) {
        #pragma unroll
        for (int it = 0; it < 4; it++) {
            const int idx = tid + it * 256;     // 0..1023
            const int row = idx >> 3;           // 0..127
            const int c4  = (idx & 7) * 4;      // 0..28
            float4 a = *(const float4*)&Qh[(size_t)(m0 + row) * 64 + k0 + c4];
            As[c4 + 0][row] = a.x; As[c4 + 1][row] = a.y;
            As[c4 + 2][row] = a.z; As[c4 + 3][row] = a.w;
            float4 b = *(const float4*)&Kh[(size_t)(n0 + row) * 64 + k0 + c4];
            Bs[c4 + 0][row] = b.x; Bs[c4 + 1][row] = b.y;
            Bs[c4 + 2][row] = b.z; Bs[c4 + 3][row] = b.w;
        }
        __syncthreads();

        #pragma unroll
        for (int kk = 0; kk < 32; kk++) {
            float4 a0 = *(const float4*)&As[kk][ty * 8];
            float4 a1 = *(const float4*)&As[kk][ty * 8 + 4];
            float4 b0 = *(const float4*)&Bs[kk][tx * 8];
            float4 b1 = *(const float4*)&Bs[kk][tx * 8 + 4];
            float av[8] = {a0.x,a0.y,a0.z,a0.w,a1.x,a1.y,a1.z,a1.w};
            float bv[8] = {b0.x,b0.y,b0.z,b0.w,b1.x,b1.y,b1.z,b1.w};
            #pragma unroll
            for (int i = 0; i < 8; i++)
                #pragma unroll
                for (int j = 0; j < 8; j++)
                    acc[i][j] += av[i] * bv[j];
        }
        __syncthreads();
    }

    // epilogue: scale + mask + store s; per-row local max & sumexp
    const int b_ = bh >> 4;
    const int* mb = mask + (size_t)b_ * Sc * Sc;
    const float scale = 0.125f;
    float mx[8], le[8];

    #pragma unroll
    for (int i = 0; i < 8; i++) {
        const int q = m0 + ty * 8 + i;
        const int k = n0 + tx * 8;
        const int4 mm0 = *(const int4*)&mb[(size_t)q * Sc + k];
        const int4 mm1 = *(const int4*)&mb[(size_t)q * Sc + k + 4];
        acc[i][0] = (mm0.x == 0) ? -1e9f : acc[i][0] * scale;
        acc[i][1] = (mm0.y == 0) ? -1e9f : acc[i][1] * scale;
        acc[i][2] = (mm0.z == 0) ? -1e9f : acc[i][2] * scale;
        acc[i][3] = (mm0.w == 0) ? -1e9f : acc[i][3] * scale;
        acc[i][4] = (mm1.x == 0) ? -1e9f : acc[i][4] * scale;
        acc[i][5] = (mm1.y == 0) ? -1e9f : acc[i][5] * scale;
        acc[i][6] = (mm1.z == 0) ? -1e9f : acc[i][6] * scale;
        acc[i][7] = (mm1.w == 0) ? -1e9f : acc[i][7] * scale;
        float* dst = &Ph[(size_t)q * Sc + k];
        *(float4*)dst = make_float4(acc[i][0], acc[i][1], acc[i][2], acc[i][3]);
        *(float4*)(dst + 4) = make_float4(acc[i][4], acc[i][5], acc[i][6], acc[i][7]);
        float m8 = acc[i][0];
        #pragma unroll
        for (int j = 1; j < 8; j++) m8 = fmaxf(m8, acc[i][j]);
        mx[i] = m8;
    }
    // reduce max over the 16 tx lanes (stays within half-warp)
    #pragma unroll
    for (int i = 0; i < 8; i++) {
        #pragma unroll
        for (int o = 8; o > 0; o >>= 1)
            mx[i] = fmaxf(mx[i], __shfl_xor_sync(0xFFFFFFFFu, mx[i], o));
    }
    // local sumexp against final tile max
    #pragma unroll
    for (int i = 0; i < 8; i++) {
        float s = 0.0f;
        #pragma unroll
        for (int j = 0; j < 8; j++)
            s += exp2f((acc[i][j] - mx[i]) * LOG2E);
        #pragma unroll
        for (int o = 8; o > 0; o >>= 1)
            s += __shfl_xor_sync(0xFFFFFFFFu, s, o);
        le[i] = s;
    }
    if (tx == 0) {
        #pragma unroll
        for (int i = 0; i < 8; i++) {
            const int q = m0 + ty * 8 + i;
            const size_t pidx = ((size_t)bh * Sc + q) * 16 + blockIdx.y;
            g_pm[pidx] = mx[i];
            g_pl[pidx] = le[i];
        }
    }
}

// ---------------------------------------------------------------------------
// Combine 16 (m,l) partials per row -> final m, 1/l  (log-sum-exp merge)
// ---------------------------------------------------------------------------
__global__ __launch_bounds__(256) void reduce_ml_kernel()
{
    const size_t r = (size_t)blockIdx.x * 256 + threadIdx.x;   // 0..131071
    float m = -3.4e38f;
    float pm[16];
    #pragma unroll
    for (int t = 0; t < 16; t++) {
        pm[t] = g_pm[r * 16 + t];
        m = fmaxf(m, pm[t]);
    }
    float l = 0.0f;
    #pragma unroll
    for (int t = 0; t < 16; t++)
        l += g_pl[r * 16 + t] * exp2f((pm[t] - m) * LOG2E);
    g_M[r]  = m;
    g_Li[r] = 1.0f / l;
}

// ---------------------------------------------------------------------------
// PV: reads raw s, computes p = exp(s-m)/l (writes normalized attn in place),
// accumulates ctx = p @ V.  Per CTA: 128 q rows x full N=64, K streamed BK=32.
// ---------------------------------------------------------------------------
__global__ __launch_bounds__(256) void pv_kernel(
    float* __restrict__ attn, const float* __restrict__ V,
    float* __restrict__ ctx)
{
    const int bh = blockIdx.x;
    const int m0 = blockIdx.y * 128;
    float* Ph = attn + (size_t)bh * Sc * Sc;
    const float* Vh = V + (size_t)bh * Sc * Dc;

    __shared__ float As[32][132];   // p transposed [k][m]
    __shared__ float Bs[32][64];    // V [k][n]
    __shared__ float sm[128], sl[128];

    const int tid = threadIdx.x;
    const int tx  = tid & 7;          // 8 col groups of 8
    const int ty  = tid >> 3;         // 32 row groups of 4

    if (tid < 128) {
        const size_t r = (size_t)bh * Sc + m0 + tid;
        sm[tid] = g_M[r];
        sl[tid] = g_Li[r];
    }
    __syncthreads();

    float acc[4][8] = {};

    for (int k0 = 0; k0 < 2048; k0 += 32) {
        #pragma unroll
        for (int it = 0; it < 4; it++) {
            const int idx = tid + it * 256;     // 0..1023
            const int row = idx >> 3;           // 0..127
            const int c4  = (idx & 7) * 4;      // 0..28
            float* gp = &Ph[(size_t)(m0 + row) * Sc + k0 + c4];
            float4 s = *(const float4*)gp;
            const float mr = sm[row];
            const float il = sl[row];
            float4 p;
            p.x = exp2f((s.x - mr) * LOG2E) * il;
            p.y = exp2f((s.y - mr) * LOG2E) * il;
            p.z = exp2f((s.z - mr) * LOG2E) * il;
            p.w = exp2f((s.w - mr) * LOG2E) * il;
            *(float4*)gp = p;                   // normalized attn out
            As[c4 + 0][row] = p.x; As[c4 + 1][row] = p.y;
            As[c4 + 2][row] = p.z; As[c4 + 3][row] = p.w;
        }
        #pragma unroll
        for (int it = 0; it < 2; it++) {
            const int idx = tid + it * 256;     // 0..511
            const int vr  = idx >> 4;           // 0..31
            const int vc  = (idx & 15) * 4;     // 0..60
            *(float4*)&Bs[vr][vc] = *(const float4*)&Vh[(size_t)(k0 + vr) * 64 + vc];
        }
        __syncthreads();

        #pragma unroll
        for (int kk = 0; kk < 32; kk++) {
            float4 a = *(const float4*)&As[kk][ty * 4];
            float4 b0 = *(const float4*)&Bs[kk][tx * 8];
            float4 b1 = *(const float4*)&Bs[kk][tx * 8 + 4];
            float av[4] = {a.x,a.y,a.z,a.w};
            float bv[8] = {b0.x,b0.y,b0.z,b0.w,b1.x,b1.y,b1.z,b1.w};
            #pragma unroll
            for (int i = 0; i < 4; i++)
                #pragma unroll
                for (int j = 0; j < 8; j++)
                    acc[i][j] += av[i] * bv[j];
        }
        __syncthreads();
    }

    const int b_ = bh >> 4;
    const int h  = bh & 15;
    #pragma unroll
    for (int i = 0; i < 4; i++) {
        const int q = m0 + ty * 4 + i;
        float* dst = &ctx[((size_t)b_ * 2048 + q) * 1024 + h * 64 + tx * 8];
        *(float4*)dst       = make_float4(acc[i][0], acc[i][1], acc[i][2], acc[i][3]);
        *(float4*)(dst + 4) = make_float4(acc[i][4], acc[i][5], acc[i][6], acc[i][7]);
    }
}

// ---------------------------------------------------------------------------
extern "C" void kernel_launch(void* const* d_in, const int* in_sizes, int n_in,
                              void* d_out, int out_size)
{
    (void)in_sizes; (void)n_in; (void)out_size;

    const float* query  = (const float*)d_in[0];
    const float* key_in = (const float*)d_in[1];
    const float* value  = (const float*)d_in[2];
    const int*   mask   = (const int*)  d_in[3];
    const float* w_q    = (const float*)d_in[4];
    const float* b_q    = (const float*)d_in[5];
    const float* w_k    = (const float*)d_in[6];
    const float* b_k    = (const float*)d_in[7];
    const float* w_v    = (const float*)d_in[8];
    const float* b_v    = (const float*)d_in[9];

    float* ctx  = (float*)d_out;
    float* attn = (float*)d_out + (size_t)Bc * Sc * HIDc;

    float *Q, *K, *V;
    cudaGetSymbolAddress((void**)&Q, g_Q);
    cudaGetSymbolAddress((void**)&K, g_K);
    cudaGetSymbolAddress((void**)&V, g_V);

    dim3 gp(HIDc / 128, MROWS / 128);            // (8, 64)
    proj_kernel<<<gp, 256>>>(query,  w_q, b_q, Q);
    proj_kernel<<<gp, 256>>>(key_in, w_k, b_k, K);
    proj_kernel<<<gp, 256>>>(value,  w_v, b_v, V);

    dim3 gs(BHc, Sc / 128, Sc / 128);            // (64, 16, 16) bh fastest
    scores_kernel<<<gs, 256>>>(Q, K, mask, attn);

    reduce_ml_kernel<<<(BHc * Sc) / 256, 256>>>();

    dim3 gv(BHc, Sc / 128);                      // (64, 16)
    pv_kernel<<<gv, 256>>>(attn, V, ctx);
}

// round 4
// speedup vs baseline: 1.4080x; 1.4080x over previous
#include <cuda_runtime.h>
#include <math.h>

#define Bc   4
#define Sc   2048
#define HIDc 1024
#define Hc   16
#define Dc   64
#define MROWS (Bc*Sc)        // 8192
#define BHc  (Bc*Hc)         // 64
#define LOG2E 1.4426950408889634f

// Scratch (allocation-free __device__ globals)
__device__ float g_Q[(size_t)BHc * Sc * Dc];
__device__ float g_K[(size_t)BHc * Sc * Dc];
__device__ float g_V[(size_t)BHc * Sc * Dc];
__device__ float g_pm[(size_t)BHc * Sc * 16];   // partial row max  [bh][q][ntile]
__device__ float g_pl[(size_t)BHc * Sc * 16];   // partial sumexp   [bh][q][ntile]
__device__ float g_M [(size_t)BHc * Sc];        // final row max
__device__ float g_Li[(size_t)BHc * Sc];        // final 1/l

// ---------------------------------------------------------------------------
// tf32 helpers
// ---------------------------------------------------------------------------
__device__ __forceinline__ unsigned f2tf32(float x) {
    unsigned r;
    asm("cvt.rna.tf32.f32 %0, %1;" : "=r"(r) : "f"(x));
    return r;
}
__device__ __forceinline__ void split_tf32(float x, unsigned& hi, unsigned& lo) {
    hi = f2tf32(x);
    lo = f2tf32(x - __uint_as_float(hi));
}
__device__ __forceinline__ void mma_tf32(float c[4], const unsigned a[4], const unsigned b[2]) {
    asm("mma.sync.aligned.m16n8k8.row.col.f32.tf32.tf32.f32 "
        "{%0,%1,%2,%3},{%4,%5,%6,%7},{%8,%9},{%0,%1,%2,%3};"
        : "+f"(c[0]), "+f"(c[1]), "+f"(c[2]), "+f"(c[3])
        : "r"(a[0]), "r"(a[1]), "r"(a[2]), "r"(a[3]), "r"(b[0]), "r"(b[1]));
}

// ---------------------------------------------------------------------------
// Projection GEMM: C[m,n] = sum_k X[m,k]*W[n,k] + bias[n], split-tf32 (3 mma)
// CTA 128x128, BK=32, 8 warps (4m x 2n), warp tile 32x64.
// Output permuted into [B, H, S, D].
// ---------------------------------------------------------------------------
__global__ __launch_bounds__(256) void proj_kernel(
    const float* __restrict__ X, const float* __restrict__ W,
    const float* __restrict__ bias, float* __restrict__ out)
{
    __shared__ float Xs[32][133];
    __shared__ float Ws[32][133];

    const int tid  = threadIdx.x;
    const int lane = tid & 31;
    const int warp = tid >> 5;
    const int g    = lane >> 2;
    const int t4   = lane & 3;
    const int wm   = (warp >> 1) * 32;
    const int wn   = (warp & 1) * 64;
    const int m0   = blockIdx.y * 128;
    const int n0   = blockIdx.x * 128;

    float acc[2][8][4] = {};

    for (int k0 = 0; k0 < 1024; k0 += 32) {
        #pragma unroll
        for (int it = 0; it < 4; it++) {
            const int idx = tid + it * 256;      // 0..1023
            const int row = idx >> 3;            // 0..127
            const int c4  = (idx & 7) * 4;       // 0..28
            float4 a = *(const float4*)&X[(size_t)(m0 + row) * 1024 + k0 + c4];
            Xs[c4 + 0][row] = a.x; Xs[c4 + 1][row] = a.y;
            Xs[c4 + 2][row] = a.z; Xs[c4 + 3][row] = a.w;
            float4 b = *(const float4*)&W[(size_t)(n0 + row) * 1024 + k0 + c4];
            Ws[c4 + 0][row] = b.x; Ws[c4 + 1][row] = b.y;
            Ws[c4 + 2][row] = b.z; Ws[c4 + 3][row] = b.w;
        }
        __syncthreads();

        #pragma unroll
        for (int ks = 0; ks < 4; ks++) {
            const int kb = ks * 8;
            unsigned ah[2][4], al[2][4];
            #pragma unroll
            for (int i = 0; i < 2; i++) {
                const int r = wm + i * 16 + g;
                split_tf32(Xs[kb + t4    ][r    ], ah[i][0], al[i][0]);
                split_tf32(Xs[kb + t4    ][r + 8], ah[i][1], al[i][1]);
                split_tf32(Xs[kb + t4 + 4][r    ], ah[i][2], al[i][2]);
                split_tf32(Xs[kb + t4 + 4][r + 8], ah[i][3], al[i][3]);
            }
            #pragma unroll
            for (int j = 0; j < 8; j++) {
                unsigned bh_[2], bl_[2];
                const int c = wn + j * 8 + g;
                split_tf32(Ws[kb + t4    ][c], bh_[0], bl_[0]);
                split_tf32(Ws[kb + t4 + 4][c], bh_[1], bl_[1]);
                #pragma unroll
                for (int i = 0; i < 2; i++) {
                    mma_tf32(acc[i][j], al[i], bh_);
                    mma_tf32(acc[i][j], ah[i], bl_);
                    mma_tf32(acc[i][j], ah[i], bh_);
                }
            }
        }
        __syncthreads();
    }

    #pragma unroll
    for (int i = 0; i < 2; i++) {
        #pragma unroll
        for (int j = 0; j < 8; j++) {
            const int n = n0 + wn + j * 8 + t4 * 2;
            const int h = n >> 6;
            const int d = n & 63;
            const float bv0 = bias[n];
            const float bv1 = bias[n + 1];
            const int m1 = m0 + wm + i * 16 + g;
            {
                const int b_ = m1 >> 11, s = m1 & 2047;
                *(float2*)&out[(((size_t)b_ * 16 + h) * 2048 + s) * 64 + d] =
                    make_float2(acc[i][j][0] + bv0, acc[i][j][1] + bv1);
            }
            {
                const int m2 = m1 + 8;
                const int b_ = m2 >> 11, s = m2 & 2047;
                *(float2*)&out[(((size_t)b_ * 16 + h) * 2048 + s) * 64 + d] =
                    make_float2(acc[i][j][2] + bv0, acc[i][j][3] + bv1);
            }
        }
    }
}

// ---------------------------------------------------------------------------
// Scores: s = scale*Q.K^T (split-tf32), mask fill, store raw s, emit per-row
// per-128-col-block (max, sumexp) partials.
// CTA 128x128, 8 warps each 16 rows x 128 cols. Grid: (bh, ntile, mtile).
// ---------------------------------------------------------------------------
__global__ __launch_bounds__(256) void scores_kernel(
    const float* __restrict__ Q, const float* __restrict__ K,
    const int* __restrict__ mask, float* __restrict__ attn)
{
    const int bh = blockIdx.x;
    const int n0 = blockIdx.y * 128;
    const int m0 = blockIdx.z * 128;
    const float* Qh = Q + (size_t)bh * Sc * Dc;
    const float* Kh = K + (size_t)bh * Sc * Dc;
    float* Ph = attn + (size_t)bh * Sc * Sc;

    __shared__ float Qs[32][133];
    __shared__ float Ks[32][133];

    const int tid  = threadIdx.x;
    const int lane = tid & 31;
    const int warp = tid >> 5;
    const int g    = lane >> 2;
    const int t4   = lane & 3;
    const int mw   = warp * 16;

    float acc[16][4] = {};

    #pragma unroll
    for (int k0 = 0; k0 < 64; k0 += 32) {
        #pragma unroll
        for (int it = 0; it < 4; it++) {
            const int idx = tid + it * 256;
            const int row = idx >> 3;
            const int c4  = (idx & 7) * 4;
            float4 a = *(const float4*)&Qh[(size_t)(m0 + row) * 64 + k0 + c4];
            Qs[c4 + 0][row] = a.x; Qs[c4 + 1][row] = a.y;
            Qs[c4 + 2][row] = a.z; Qs[c4 + 3][row] = a.w;
            float4 b = *(const float4*)&Kh[(size_t)(n0 + row) * 64 + k0 + c4];
            Ks[c4 + 0][row] = b.x; Ks[c4 + 1][row] = b.y;
            Ks[c4 + 2][row] = b.z; Ks[c4 + 3][row] = b.w;
        }
        __syncthreads();

        #pragma unroll
        for (int ks = 0; ks < 4; ks++) {
            const int kb = ks * 8;
            unsigned ah[4], al[4];
            const int r = mw + g;
            split_tf32(Qs[kb + t4    ][r    ], ah[0], al[0]);
            split_tf32(Qs[kb + t4    ][r + 8], ah[1], al[1]);
            split_tf32(Qs[kb + t4 + 4][r    ], ah[2], al[2]);
            split_tf32(Qs[kb + t4 + 4][r + 8], ah[3], al[3]);
            #pragma unroll
            for (int j = 0; j < 16; j++) {
                unsigned bh_[2], bl_[2];
                const int c = j * 8 + g;
                split_tf32(Ks[kb + t4    ][c], bh_[0], bl_[0]);
                split_tf32(Ks[kb + t4 + 4][c], bh_[1], bl_[1]);
                mma_tf32(acc[j], al, bh_);
                mma_tf32(acc[j], ah, bl_);
                mma_tf32(acc[j], ah, bh_);
            }
        }
        __syncthreads();
    }

    // epilogue: scale + mask + store raw s; per-row max & sumexp partials
    const int b_ = bh >> 4;
    const int* mb = mask + (size_t)b_ * Sc * Sc;
    const float scale = 0.125f;
    const int r0 = m0 + mw + g;
    const int r1 = r0 + 8;

    float mx0 = -3.4e38f, mx1 = -3.4e38f;
    #pragma unroll
    for (int j = 0; j < 16; j++) {
        const int col = n0 + j * 8 + t4 * 2;
        const int2 mm0 = *(const int2*)&mb[(size_t)r0 * Sc + col];
        const int2 mm1 = *(const int2*)&mb[(size_t)r1 * Sc + col];
        acc[j][0] = mm0.x ? acc[j][0] * scale : -1e9f;
        acc[j][1] = mm0.y ? acc[j][1] * scale : -1e9f;
        acc[j][2] = mm1.x ? acc[j][2] * scale : -1e9f;
        acc[j][3] = mm1.y ? acc[j][3] * scale : -1e9f;
        *(float2*)&Ph[(size_t)r0 * Sc + col] = make_float2(acc[j][0], acc[j][1]);
        *(float2*)&Ph[(size_t)r1 * Sc + col] = make_float2(acc[j][2], acc[j][3]);
        mx0 = fmaxf(mx0, fmaxf(acc[j][0], acc[j][1]));
        mx1 = fmaxf(mx1, fmaxf(acc[j][2], acc[j][3]));
    }
    mx0 = fmaxf(mx0, __shfl_xor_sync(0xFFFFFFFFu, mx0, 1));
    mx0 = fmaxf(mx0, __shfl_xor_sync(0xFFFFFFFFu, mx0, 2));
    mx1 = fmaxf(mx1, __shfl_xor_sync(0xFFFFFFFFu, mx1, 1));
    mx1 = fmaxf(mx1, __shfl_xor_sync(0xFFFFFFFFu, mx1, 2));

    float s0 = 0.0f, s1 = 0.0f;
    #pragma unroll
    for (int j = 0; j < 16; j++) {
        s0 += exp2f((acc[j][0] - mx0) * LOG2E) + exp2f((acc[j][1] - mx0) * LOG2E);
        s1 += exp2f((acc[j][2] - mx1) * LOG2E) + exp2f((acc[j][3] - mx1) * LOG2E);
    }
    s0 += __shfl_xor_sync(0xFFFFFFFFu, s0, 1);
    s0 += __shfl_xor_sync(0xFFFFFFFFu, s0, 2);
    s1 += __shfl_xor_sync(0xFFFFFFFFu, s1, 1);
    s1 += __shfl_xor_sync(0xFFFFFFFFu, s1, 2);

    if (t4 == 0) {
        g_pm[((size_t)bh * Sc + r0) * 16 + blockIdx.y] = mx0;
        g_pl[((size_t)bh * Sc + r0) * 16 + blockIdx.y] = s0;
        g_pm[((size_t)bh * Sc + r1) * 16 + blockIdx.y] = mx1;
        g_pl[((size_t)bh * Sc + r1) * 16 + blockIdx.y] = s1;
    }
}

// ---------------------------------------------------------------------------
// Combine 16 (m,l) partials per row -> final m, 1/l
// ---------------------------------------------------------------------------
__global__ __launch_bounds__(256) void reduce_ml_kernel()
{
    const size_t r = (size_t)blockIdx.x * 256 + threadIdx.x;
    float m = -3.4e38f;
    float pm[16];
    #pragma unroll
    for (int t = 0; t < 16; t++) {
        pm[t] = g_pm[r * 16 + t];
        m = fmaxf(m, pm[t]);
    }
    float l = 0.0f;
    #pragma unroll
    for (int t = 0; t < 16; t++)
        l += g_pl[r * 16 + t] * exp2f((pm[t] - m) * LOG2E);
    g_M[r]  = m;
    g_Li[r] = 1.0f / l;
}

// ---------------------------------------------------------------------------
// PV: normalize p = exp(s-m)*invl (write attn in place), ctx = p @ V.
// Single tf32 mma. CTA 128 rows x 64 cols, 8 warps each 16 rows.
// ---------------------------------------------------------------------------
__global__ __launch_bounds__(256) void pv_kernel(
    float* __restrict__ attn, const float* __restrict__ V,
    float* __restrict__ ctx)
{
    const int bh = blockIdx.x;
    const int m0 = blockIdx.y * 128;
    float* Ph = attn + (size_t)bh * Sc * Sc;
    const float* Vh = V + (size_t)bh * Sc * Dc;

    __shared__ float Ps[32][133];
    __shared__ float Vs[32][68];
    __shared__ float smx[128], sli[128];

    const int tid  = threadIdx.x;
    const int lane = tid & 31;
    const int warp = tid >> 5;
    const int g    = lane >> 2;
    const int t4   = lane & 3;
    const int mw   = warp * 16;

    if (tid < 128) {
        const size_t r = (size_t)bh * Sc + m0 + tid;
        smx[tid] = g_M[r];
        sli[tid] = g_Li[r];
    }
    __syncthreads();

    float acc[8][4] = {};

    for (int k0 = 0; k0 < 2048; k0 += 32) {
        #pragma unroll
        for (int it = 0; it < 4; it++) {
            const int idx = tid + it * 256;
            const int row = idx >> 3;
            const int c4  = (idx & 7) * 4;
            float* gp = &Ph[(size_t)(m0 + row) * Sc + k0 + c4];
            float4 s = *(const float4*)gp;
            const float mr = smx[row];
            const float il = sli[row];
            float4 p;
            p.x = exp2f((s.x - mr) * LOG2E) * il;
            p.y = exp2f((s.y - mr) * LOG2E) * il;
            p.z = exp2f((s.z - mr) * LOG2E) * il;
            p.w = exp2f((s.w - mr) * LOG2E) * il;
            *(float4*)gp = p;
            Ps[c4 + 0][row] = p.x; Ps[c4 + 1][row] = p.y;
            Ps[c4 + 2][row] = p.z; Ps[c4 + 3][row] = p.w;
        }
        #pragma unroll
        for (int it = 0; it < 2; it++) {
            const int idx = tid + it * 256;
            const int vr  = idx >> 4;
            const int vc  = (idx & 15) * 4;
            *(float4*)&Vs[vr][vc] = *(const float4*)&Vh[(size_t)(k0 + vr) * 64 + vc];
        }
        __syncthreads();

        #pragma unroll
        for (int ks = 0; ks < 4; ks++) {
            const int kb = ks * 8;
            unsigned a[4];
            const int r = mw + g;
            a[0] = f2tf32(Ps[kb + t4    ][r    ]);
            a[1] = f2tf32(Ps[kb + t4    ][r + 8]);
            a[2] = f2tf32(Ps[kb + t4 + 4][r    ]);
            a[3] = f2tf32(Ps[kb + t4 + 4][r + 8]);
            #pragma unroll
            for (int j = 0; j < 8; j++) {
                unsigned b[2];
                b[0] = f2tf32(Vs[kb + t4    ][j * 8 + g]);
                b[1] = f2tf32(Vs[kb + t4 + 4][j * 8 + g]);
                mma_tf32(acc[j], a, b);
            }
        }
        __syncthreads();
    }

    const int b_ = bh >> 4;
    const int h  = bh & 15;
    const int r0 = m0 + mw + g;
    const int r1 = r0 + 8;
    #pragma unroll
    for (int j = 0; j < 8; j++) {
        const int d = j * 8 + t4 * 2;
        *(float2*)&ctx[((size_t)b_ * 2048 + r0) * 1024 + h * 64 + d] =
            make_float2(acc[j][0], acc[j][1]);
        *(float2*)&ctx[((size_t)b_ * 2048 + r1) * 1024 + h * 64 + d] =
            make_float2(acc[j][2], acc[j][3]);
    }
}

// ---------------------------------------------------------------------------
extern "C" void kernel_launch(void* const* d_in, const int* in_sizes, int n_in,
                              void* d_out, int out_size)
{
    (void)in_sizes; (void)n_in; (void)out_size;

    const float* query  = (const float*)d_in[0];
    const float* key_in = (const float*)d_in[1];
    const float* value  = (const float*)d_in[2];
    const int*   mask   = (const int*)  d_in[3];
    const float* w_q    = (const float*)d_in[4];
    const float* b_q    = (const float*)d_in[5];
    const float* w_k    = (const float*)d_in[6];
    const float* b_k    = (const float*)d_in[7];
    const float* w_v    = (const float*)d_in[8];
    const float* b_v    = (const float*)d_in[9];

    float* ctx  = (float*)d_out;
    float* attn = (float*)d_out + (size_t)Bc * Sc * HIDc;

    float *Q, *K, *V;
    cudaGetSymbolAddress((void**)&Q, g_Q);
    cudaGetSymbolAddress((void**)&K, g_K);
    cudaGetSymbolAddress((void**)&V, g_V);

    dim3 gp(HIDc / 128, MROWS / 128);            // (8, 64)
    proj_kernel<<<gp, 256>>>(query,  w_q, b_q, Q);
    proj_kernel<<<gp, 256>>>(key_in, w_k, b_k, K);
    proj_kernel<<<gp, 256>>>(value,  w_v, b_v, V);

    dim3 gs(BHc, Sc / 128, Sc / 128);            // (64, 16, 16)
    scores_kernel<<<gs, 256>>>(Q, K, mask, attn);

    reduce_ml_kernel<<<(BHc * Sc) / 256, 256>>>();

    dim3 gv(BHc, Sc / 128);                      // (64, 16)
    pv_kernel<<<gv, 256>>>(attn, V, ctx);
}

// round 5
// speedup vs baseline: 1.4124x; 1.0031x over previous
#include <cuda_runtime.h>
#include <math.h>

#define Bc   4
#define Sc   2048
#define HIDc 1024
#define Hc   16
#define Dc   64
#define MROWS (Bc*Sc)        // 8192
#define BHc  (Bc*Hc)         // 64
#define LOG2E 1.4426950408889634f

// Scratch (allocation-free __device__ globals)
__device__ float g_Q[(size_t)BHc * Sc * Dc];
__device__ float g_K[(size_t)BHc * Sc * Dc];
__device__ float g_V[(size_t)BHc * Sc * Dc];
__device__ float g_pm[(size_t)BHc * Sc * 16];   // partial row max  [bh][q][ntile]
__device__ float g_pl[(size_t)BHc * Sc * 16];   // partial sumexp   [bh][q][ntile]
__device__ float g_M [(size_t)BHc * Sc];        // final row max
__device__ float g_Li[(size_t)BHc * Sc];        // final 1/l

// ---------------------------------------------------------------------------
// tf32 helpers
// ---------------------------------------------------------------------------
__device__ __forceinline__ unsigned f2tf32(float x) {
    unsigned r;
    asm("cvt.rna.tf32.f32 %0, %1;" : "=r"(r) : "f"(x));
    return r;
}
__device__ __forceinline__ void split_tf32(float x, unsigned& hi, unsigned& lo) {
    hi = f2tf32(x);
    lo = f2tf32(x - __uint_as_float(hi));
}
__device__ __forceinline__ void mma_tf32(float c[4], const unsigned a[4], const unsigned b[2]) {
    asm("mma.sync.aligned.m16n8k8.row.col.f32.tf32.tf32.f32 "
        "{%0,%1,%2,%3},{%4,%5,%6,%7},{%8,%9},{%0,%1,%2,%3};"
        : "+f"(c[0]), "+f"(c[1]), "+f"(c[2]), "+f"(c[3])
        : "r"(a[0]), "r"(a[1]), "r"(a[2]), "r"(a[3]), "r"(b[0]), "r"(b[1]));
}

// ---------------------------------------------------------------------------
// Projection GEMM: C[m,n] = sum_k X[m,k]*W[n,k] + bias[n], split-tf32 (3 mma).
// CTA 64x128, BK=32, 4 warps (2m x 2n), warp tile 32x64.
// W pre-split to tf32 hi/lo in SMEM; X split in registers.
// Output permuted into [B, H, S, D].
// ---------------------------------------------------------------------------
__global__ __launch_bounds__(128) void proj_kernel(
    const float* __restrict__ X, const float* __restrict__ W,
    const float* __restrict__ bias, float* __restrict__ out)
{
    __shared__ float    Xs[32][68];
    __shared__ unsigned Wh[32][132];
    __shared__ unsigned Wl[32][132];

    const int tid  = threadIdx.x;
    const int lane = tid & 31;
    const int warp = tid >> 5;
    const int g    = lane >> 2;
    const int t4   = lane & 3;
    const int wm   = (warp >> 1) * 32;
    const int wn   = (warp & 1) * 64;
    const int m0   = blockIdx.y * 64;
    const int n0   = blockIdx.x * 128;

    float acc[2][8][4] = {};

    for (int k0 = 0; k0 < 1024; k0 += 32) {
        // X tile: 64 rows x 32 k
        #pragma unroll
        for (int it = 0; it < 4; it++) {
            const int idx = tid + it * 128;      // 0..511
            const int row = idx >> 3;            // 0..63
            const int c4  = (idx & 7) * 4;       // 0..28
            float4 a = *(const float4*)&X[(size_t)(m0 + row) * 1024 + k0 + c4];
            Xs[c4 + 0][row] = a.x; Xs[c4 + 1][row] = a.y;
            Xs[c4 + 2][row] = a.z; Xs[c4 + 3][row] = a.w;
        }
        // W tile: 128 rows x 32 k, pre-split hi/lo
        #pragma unroll
        for (int it = 0; it < 8; it++) {
            const int idx = tid + it * 128;      // 0..1023
            const int row = idx >> 3;            // 0..127
            const int c4  = (idx & 7) * 4;       // 0..28
            float4 b = *(const float4*)&W[(size_t)(n0 + row) * 1024 + k0 + c4];
            unsigned h0,l0,h1,l1,h2,l2,h3,l3;
            split_tf32(b.x, h0, l0); split_tf32(b.y, h1, l1);
            split_tf32(b.z, h2, l2); split_tf32(b.w, h3, l3);
            Wh[c4 + 0][row] = h0; Wl[c4 + 0][row] = l0;
            Wh[c4 + 1][row] = h1; Wl[c4 + 1][row] = l1;
            Wh[c4 + 2][row] = h2; Wl[c4 + 2][row] = l2;
            Wh[c4 + 3][row] = h3; Wl[c4 + 3][row] = l3;
        }
        __syncthreads();

        #pragma unroll
        for (int ks = 0; ks < 4; ks++) {
            const int kb = ks * 8;
            unsigned ah[2][4], al[2][4];
            #pragma unroll
            for (int i = 0; i < 2; i++) {
                const int r = wm + i * 16 + g;
                split_tf32(Xs[kb + t4    ][r    ], ah[i][0], al[i][0]);
                split_tf32(Xs[kb + t4    ][r + 8], ah[i][1], al[i][1]);
                split_tf32(Xs[kb + t4 + 4][r    ], ah[i][2], al[i][2]);
                split_tf32(Xs[kb + t4 + 4][r + 8], ah[i][3], al[i][3]);
            }
            #pragma unroll
            for (int j = 0; j < 8; j++) {
                const int c = wn + j * 8 + g;
                unsigned bh_[2], bl_[2];
                bh_[0] = Wh[kb + t4    ][c];
                bh_[1] = Wh[kb + t4 + 4][c];
                bl_[0] = Wl[kb + t4    ][c];
                bl_[1] = Wl[kb + t4 + 4][c];
                #pragma unroll
                for (int i = 0; i < 2; i++) {
                    mma_tf32(acc[i][j], al[i], bh_);
                    mma_tf32(acc[i][j], ah[i], bl_);
                    mma_tf32(acc[i][j], ah[i], bh_);
                }
            }
        }
        __syncthreads();
    }

    #pragma unroll
    for (int i = 0; i < 2; i++) {
        #pragma unroll
        for (int j = 0; j < 8; j++) {
            const int n = n0 + wn + j * 8 + t4 * 2;
            const int h = n >> 6;
            const int d = n & 63;
            const float bv0 = bias[n];
            const float bv1 = bias[n + 1];
            const int m1 = m0 + wm + i * 16 + g;
            {
                const int b_ = m1 >> 11, s = m1 & 2047;
                *(float2*)&out[(((size_t)b_ * 16 + h) * 2048 + s) * 64 + d] =
                    make_float2(acc[i][j][0] + bv0, acc[i][j][1] + bv1);
            }
            {
                const int m2 = m1 + 8;
                const int b_ = m2 >> 11, s = m2 & 2047;
                *(float2*)&out[(((size_t)b_ * 16 + h) * 2048 + s) * 64 + d] =
                    make_float2(acc[i][j][2] + bv0, acc[i][j][3] + bv1);
            }
        }
    }
}

// ---------------------------------------------------------------------------
// Scores: s = scale*Q.K^T (split-tf32), mask fill, store raw s, emit per-row
// per-128-col-block (max, sumexp) partials.
// CTA 64x128, 4 warps each 16 rows x 128 cols. K pre-split hi/lo in SMEM.
// Grid: (bh, ntile=16, mtile=32).
// ---------------------------------------------------------------------------
__global__ __launch_bounds__(128) void scores_kernel(
    const float* __restrict__ Q, const float* __restrict__ K,
    const int* __restrict__ mask, float* __restrict__ attn)
{
    const int bh = blockIdx.x;
    const int n0 = blockIdx.y * 128;
    const int m0 = blockIdx.z * 64;
    const float* Qh = Q + (size_t)bh * Sc * Dc;
    const float* Kh_g = K + (size_t)bh * Sc * Dc;
    float* Ph = attn + (size_t)bh * Sc * Sc;

    __shared__ float    Qs[32][68];
    __shared__ unsigned Kh[32][132];
    __shared__ unsigned Kl[32][132];

    const int tid  = threadIdx.x;
    const int lane = tid & 31;
    const int warp = tid >> 5;
    const int g    = lane >> 2;
    const int t4   = lane & 3;
    const int mw   = warp * 16;

    float acc[16][4] = {};

    #pragma unroll
    for (int k0 = 0; k0 < 64; k0 += 32) {
        #pragma unroll
        for (int it = 0; it < 4; it++) {
            const int idx = tid + it * 128;      // 0..511
            const int row = idx >> 3;            // 0..63
            const int c4  = (idx & 7) * 4;
            float4 a = *(const float4*)&Qh[(size_t)(m0 + row) * 64 + k0 + c4];
            Qs[c4 + 0][row] = a.x; Qs[c4 + 1][row] = a.y;
            Qs[c4 + 2][row] = a.z; Qs[c4 + 3][row] = a.w;
        }
        #pragma unroll
        for (int it = 0; it < 8; it++) {
            const int idx = tid + it * 128;      // 0..1023
            const int row = idx >> 3;            // 0..127
            const int c4  = (idx & 7) * 4;
            float4 b = *(const float4*)&Kh_g[(size_t)(n0 + row) * 64 + k0 + c4];
            unsigned h0,l0,h1,l1,h2,l2,h3,l3;
            split_tf32(b.x, h0, l0); split_tf32(b.y, h1, l1);
            split_tf32(b.z, h2, l2); split_tf32(b.w, h3, l3);
            Kh[c4 + 0][row] = h0; Kl[c4 + 0][row] = l0;
            Kh[c4 + 1][row] = h1; Kl[c4 + 1][row] = l1;
            Kh[c4 + 2][row] = h2; Kl[c4 + 2][row] = l2;
            Kh[c4 + 3][row] = h3; Kl[c4 + 3][row] = l3;
        }
        __syncthreads();

        #pragma unroll
        for (int ks = 0; ks < 4; ks++) {
            const int kb = ks * 8;
            unsigned ah[4], al[4];
            const int r = mw + g;
            split_tf32(Qs[kb + t4    ][r    ], ah[0], al[0]);
            split_tf32(Qs[kb + t4    ][r + 8], ah[1], al[1]);
            split_tf32(Qs[kb + t4 + 4][r    ], ah[2], al[2]);
            split_tf32(Qs[kb + t4 + 4][r + 8], ah[3], al[3]);
            #pragma unroll
            for (int j = 0; j < 16; j++) {
                const int c = j * 8 + g;
                unsigned bh_[2], bl_[2];
                bh_[0] = Kh[kb + t4    ][c];
                bh_[1] = Kh[kb + t4 + 4][c];
                bl_[0] = Kl[kb + t4    ][c];
                bl_[1] = Kl[kb + t4 + 4][c];
                mma_tf32(acc[j], al, bh_);
                mma_tf32(acc[j], ah, bl_);
                mma_tf32(acc[j], ah, bh_);
            }
        }
        __syncthreads();
    }

    // epilogue: scale + mask + store raw s; per-row max & sumexp partials
    const int b_ = bh >> 4;
    const int* mb = mask + (size_t)b_ * Sc * Sc;
    const float scale = 0.125f;
    const int r0 = m0 + mw + g;
    const int r1 = r0 + 8;

    float mx0 = -3.4e38f, mx1 = -3.4e38f;
    #pragma unroll
    for (int j = 0; j < 16; j++) {
        const int col = n0 + j * 8 + t4 * 2;
        const int2 mm0 = *(const int2*)&mb[(size_t)r0 * Sc + col];
        const int2 mm1 = *(const int2*)&mb[(size_t)r1 * Sc + col];
        acc[j][0] = mm0.x ? acc[j][0] * scale : -1e9f;
        acc[j][1] = mm0.y ? acc[j][1] * scale : -1e9f;
        acc[j][2] = mm1.x ? acc[j][2] * scale : -1e9f;
        acc[j][3] = mm1.y ? acc[j][3] * scale : -1e9f;
        *(float2*)&Ph[(size_t)r0 * Sc + col] = make_float2(acc[j][0], acc[j][1]);
        *(float2*)&Ph[(size_t)r1 * Sc + col] = make_float2(acc[j][2], acc[j][3]);
        mx0 = fmaxf(mx0, fmaxf(acc[j][0], acc[j][1]));
        mx1 = fmaxf(mx1, fmaxf(acc[j][2], acc[j][3]));
    }
    mx0 = fmaxf(mx0, __shfl_xor_sync(0xFFFFFFFFu, mx0, 1));
    mx0 = fmaxf(mx0, __shfl_xor_sync(0xFFFFFFFFu, mx0, 2));
    mx1 = fmaxf(mx1, __shfl_xor_sync(0xFFFFFFFFu, mx1, 1));
    mx1 = fmaxf(mx1, __shfl_xor_sync(0xFFFFFFFFu, mx1, 2));

    float s0 = 0.0f, s1 = 0.0f;
    #pragma unroll
    for (int j = 0; j < 16; j++) {
        s0 += exp2f((acc[j][0] - mx0) * LOG2E) + exp2f((acc[j][1] - mx0) * LOG2E);
        s1 += exp2f((acc[j][2] - mx1) * LOG2E) + exp2f((acc[j][3] - mx1) * LOG2E);
    }
    s0 += __shfl_xor_sync(0xFFFFFFFFu, s0, 1);
    s0 += __shfl_xor_sync(0xFFFFFFFFu, s0, 2);
    s1 += __shfl_xor_sync(0xFFFFFFFFu, s1, 1);
    s1 += __shfl_xor_sync(0xFFFFFFFFu, s1, 2);

    if (t4 == 0) {
        g_pm[((size_t)bh * Sc + r0) * 16 + blockIdx.y] = mx0;
        g_pl[((size_t)bh * Sc + r0) * 16 + blockIdx.y] = s0;
        g_pm[((size_t)bh * Sc + r1) * 16 + blockIdx.y] = mx1;
        g_pl[((size_t)bh * Sc + r1) * 16 + blockIdx.y] = s1;
    }
}

// ---------------------------------------------------------------------------
// Combine 16 (m,l) partials per row -> final m, 1/l
// ---------------------------------------------------------------------------
__global__ __launch_bounds__(256) void reduce_ml_kernel()
{
    const size_t r = (size_t)blockIdx.x * 256 + threadIdx.x;
    float m = -3.4e38f;
    float pm[16];
    #pragma unroll
    for (int t = 0; t < 16; t++) {
        pm[t] = g_pm[r * 16 + t];
        m = fmaxf(m, pm[t]);
    }
    float l = 0.0f;
    #pragma unroll
    for (int t = 0; t < 16; t++)
        l += g_pl[r * 16 + t] * exp2f((pm[t] - m) * LOG2E);
    g_M[r]  = m;
    g_Li[r] = 1.0f / l;
}

// ---------------------------------------------------------------------------
// PV: normalize p = exp(s-m)*invl (write attn in place), ctx = p @ V.
// Single tf32 mma, P and V pre-converted to tf32 in SMEM.
// CTA 128 rows x 64 cols, 8 warps each 16 rows.
// ---------------------------------------------------------------------------
__global__ __launch_bounds__(256) void pv_kernel(
    float* __restrict__ attn, const float* __restrict__ V,
    float* __restrict__ ctx)
{
    const int bh = blockIdx.x;
    const int m0 = blockIdx.y * 128;
    float* Ph = attn + (size_t)bh * Sc * Sc;
    const float* Vh = V + (size_t)bh * Sc * Dc;

    __shared__ unsigned Ps[32][133];
    __shared__ unsigned Vs[32][68];
    __shared__ float smx[128], sli[128];

    const int tid  = threadIdx.x;
    const int lane = tid & 31;
    const int warp = tid >> 5;
    const int g    = lane >> 2;
    const int t4   = lane & 3;
    const int mw   = warp * 16;

    if (tid < 128) {
        const size_t r = (size_t)bh * Sc + m0 + tid;
        smx[tid] = g_M[r];
        sli[tid] = g_Li[r];
    }
    __syncthreads();

    float acc[8][4] = {};

    for (int k0 = 0; k0 < 2048; k0 += 32) {
        #pragma unroll
        for (int it = 0; it < 4; it++) {
            const int idx = tid + it * 256;
            const int row = idx >> 3;
            const int c4  = (idx & 7) * 4;
            float* gp = &Ph[(size_t)(m0 + row) * Sc + k0 + c4];
            float4 s = *(const float4*)gp;
            const float mr = smx[row];
            const float il = sli[row];
            float4 p;
            p.x = exp2f((s.x - mr) * LOG2E) * il;
            p.y = exp2f((s.y - mr) * LOG2E) * il;
            p.z = exp2f((s.z - mr) * LOG2E) * il;
            p.w = exp2f((s.w - mr) * LOG2E) * il;
            *(float4*)gp = p;
            Ps[c4 + 0][row] = f2tf32(p.x);
            Ps[c4 + 1][row] = f2tf32(p.y);
            Ps[c4 + 2][row] = f2tf32(p.z);
            Ps[c4 + 3][row] = f2tf32(p.w);
        }
        #pragma unroll
        for (int it = 0; it < 2; it++) {
            const int idx = tid + it * 256;
            const int vr  = idx >> 4;
            const int vc  = (idx & 15) * 4;
            float4 v = *(const float4*)&Vh[(size_t)(k0 + vr) * 64 + vc];
            Vs[vr][vc + 0] = f2tf32(v.x);
            Vs[vr][vc + 1] = f2tf32(v.y);
            Vs[vr][vc + 2] = f2tf32(v.z);
            Vs[vr][vc + 3] = f2tf32(v.w);
        }
        __syncthreads();

        #pragma unroll
        for (int ks = 0; ks < 4; ks++) {
            const int kb = ks * 8;
            unsigned a[4];
            const int r = mw + g;
            a[0] = Ps[kb + t4    ][r    ];
            a[1] = Ps[kb + t4    ][r + 8];
            a[2] = Ps[kb + t4 + 4][r    ];
            a[3] = Ps[kb + t4 + 4][r + 8];
            #pragma unroll
            for (int j = 0; j < 8; j++) {
                unsigned b[2];
                b[0] = Vs[kb + t4    ][j * 8 + g];
                b[1] = Vs[kb + t4 + 4][j * 8 + g];
                mma_tf32(acc[j], a, b);
            }
        }
        __syncthreads();
    }

    const int b_ = bh >> 4;
    const int h  = bh & 15;
    const int r0 = m0 + mw + g;
    const int r1 = r0 + 8;
    #pragma unroll
    for (int j = 0; j < 8; j++) {
        const int d = j * 8 + t4 * 2;
        *(float2*)&ctx[((size_t)b_ * 2048 + r0) * 1024 + h * 64 + d] =
            make_float2(acc[j][0], acc[j][1]);
        *(float2*)&ctx[((size_t)b_ * 2048 + r1) * 1024 + h * 64 + d] =
            make_float2(acc[j][2], acc[j][3]);
    }
}

// ---------------------------------------------------------------------------
extern "C" void kernel_launch(void* const* d_in, const int* in_sizes, int n_in,
                              void* d_out, int out_size)
{
    (void)in_sizes; (void)n_in; (void)out_size;

    const float* query  = (const float*)d_in[0];
    const float* key_in = (const float*)d_in[1];
    const float* value  = (const float*)d_in[2];
    const int*   mask   = (const int*)  d_in[3];
    const float* w_q    = (const float*)d_in[4];
    const float* b_q    = (const float*)d_in[5];
    const float* w_k    = (const float*)d_in[6];
    const float* b_k    = (const float*)d_in[7];
    const float* w_v    = (const float*)d_in[8];
    const float* b_v    = (const float*)d_in[9];

    float* ctx  = (float*)d_out;
    float* attn = (float*)d_out + (size_t)Bc * Sc * HIDc;

    float *Q, *K, *V;
    cudaGetSymbolAddress((void**)&Q, g_Q);
    cudaGetSymbolAddress((void**)&K, g_K);
    cudaGetSymbolAddress((void**)&V, g_V);

    dim3 gp(HIDc / 128, MROWS / 64);             // (8, 128)
    proj_kernel<<<gp, 128>>>(query,  w_q, b_q, Q);
    proj_kernel<<<gp, 128>>>(key_in, w_k, b_k, K);
    proj_kernel<<<gp, 128>>>(value,  w_v, b_v, V);

    dim3 gs(BHc, Sc / 128, Sc / 64);             // (64, 16, 32)
    scores_kernel<<<gs, 128>>>(Q, K, mask, attn);

    reduce_ml_kernel<<<(BHc * Sc) / 256, 256>>>();

    dim3 gv(BHc, Sc / 128);                      // (64, 16)
    pv_kernel<<<gv, 256>>>(attn, V, ctx);
}